// round 4
// baseline (speedup 1.0000x reference)
#include <cuda_runtime.h>
#include <math.h>
#include <float.h>

#define NB 8
#define NT 2048
#define NC 2048
#define NE 32
#define NH 64
#define HC (NH*NC)
#define NROWS (NB*NT)
#define KSPLIT 4

typedef unsigned long long ull;

// ---------------- scratch ----------------
__device__ __align__(16) float g_part[NB*16*NC];
__device__ float g_dots[NE + NB + NB*NE];
__device__ __align__(16) float g_wv[NB*HC];              // (b,h,c)
__device__ __align__(16) float g_wvT[NB*HC];             // (b,c,h)  transposed for GEMM1
__device__ __align__(16) float g_wo[NB*HC];              // (b,h,c)  natural [k][n] for GEMM2
__device__ __align__(16) float g_comb2[KSPLIT*NROWS*NH];

// ---------------- helpers ----------------
__device__ __forceinline__ void fma2(ull& d, ull a, ull b){
    asm("fma.rn.f32x2 %0, %1, %2, %0;" : "+l"(d) : "l"(a), "l"(b));
}
__device__ __forceinline__ ull pk2(float lo, float hi){
    ull r; asm("mov.b64 %0, {%1, %2};" : "=l"(r) : "f"(lo), "f"(hi)); return r;
}
__device__ __forceinline__ float2 upk2(ull v){
    float2 f; asm("mov.b64 {%0, %1}, %2;" : "=f"(f.x), "=f"(f.y) : "l"(v)); return f;
}
__device__ __forceinline__ float fcomp(const float4& v, int i){
    return i==0 ? v.x : (i==1 ? v.y : (i==2 ? v.z : v.w));
}
__device__ __forceinline__ int swzA(int k, int m){ return m ^ ((k ^ (m>>3)) & 7); }

#define CP_ASYNC16(dst,src) asm volatile("cp.async.cg.shared.global [%0], [%1], 16;" :: "r"(dst), "l"(src))
#define CP_COMMIT() asm volatile("cp.async.commit_group;")
#define CP_WAIT0()  asm volatile("cp.async.wait_group 0;")

__device__ __forceinline__ float wredsum(float v){
    #pragma unroll
    for (int o=16;o>0;o>>=1) v += __shfl_xor_sync(0xffffffffu, v, o);
    return v;
}
__device__ __forceinline__ float wredmax(float v){
    #pragma unroll
    for (int o=16;o>0;o>>=1) v = fmaxf(v, __shfl_xor_sync(0xffffffffu, v, o));
    return v;
}

// ---------------- 1) partial column sums over T ----------------
__global__ void k_mean(const float* __restrict__ X){
    int c = blockIdx.x*256 + threadIdx.x;
    int s = blockIdx.y, b = blockIdx.z;
    const float* p = X + ((size_t)b*NT + (size_t)s*128)*NC + c;
    float a0=0.f,a1=0.f,a2=0.f,a3=0.f;
    for (int t=0;t<128;t+=4){
        a0 += p[0]; a1 += p[NC]; a2 += p[2*NC]; a3 += p[3*NC];
        p += (size_t)4*NC;
    }
    g_part[(b*16+s)*NC + c] = (a0+a1)+(a2+a3);
}

// ---------------- 2) norms + affinity dots ----------------
__global__ void k_dots(const float* __restrict__ sim){
    __shared__ float sred[4];
    int task = blockIdx.x;
    int tid = threadIdx.x; // 128 threads
    float acc = 0.f;
    if (task < NE){
        int e = task;
        for (int c = tid; c < NC; c += 128){ float v = sim[c*NE + e]; acc += v*v; }
    } else if (task < NE+NB){
        int b = task - NE;
        for (int c = tid; c < NC; c += 128){
            float v = 0.f;
            #pragma unroll
            for (int s=0;s<16;s++) v += g_part[(b*16+s)*NC + c];
            acc += v*v;
        }
    } else {
        int p = task - NE - NB;
        int b = p >> 5, e = p & 31;
        for (int c = tid; c < NC; c += 128){
            float v = 0.f;
            #pragma unroll
            for (int s=0;s<16;s++) v += g_part[(b*16+s)*NC + c];
            acc += v * sim[c*NE + e];
        }
    }
    acc = wredsum(acc);
    if ((tid & 31) == 0) sred[tid>>5] = acc;
    __syncthreads();
    if (tid == 0) g_dots[task] = (sred[0]+sred[1])+(sred[2]+sred[3]);
}

// ---------------- 3) gating + fold into W_v/W_o ----------------
__global__ void k_weff(const float* __restrict__ gates,
                       const float* __restrict__ w_v, const float* __restrict__ o_w){
    __shared__ float r[NB*NE];
    int tid = threadIdx.x;   // 256 threads: warp = batch, lane = expert
    {
        int lane = tid & 31, b = tid >> 5;
        float nsim2 = g_dots[lane];
        float nseq2 = g_dots[NE + b];
        float dot   = g_dots[NE + NB + b*NE + lane];
        float aff = dot / sqrtf(nsim2 * nseq2);
        float sig = 1.f / (1.f + expf(-gates[lane]));
        float logit = aff - sig;
        float gated = fmaxf(logit, 0.f);
        bool  act = gated > 0.f;
        unsigned actm = __ballot_sync(0xffffffffu, act);
        bool use = act;
        if (actm == 0u){
            int rank = 0;
            #pragma unroll
            for (int e=0;e<NE;e++){
                float le = __shfl_sync(0xffffffffu, logit, e);
                rank += (le > logit) || (le == logit && e < lane);
            }
            use = rank < 16;
        }
        float v = use ? gated : -FLT_MAX;
        float mx = wredmax(v);
        float ex = use ? expf(gated - mx) : 0.f;
        float sm = wredsum(ex);
        r[tid] = ex / sm;
    }
    __syncthreads();
    int j = blockIdx.x*256 + tid;   // over HC
    float accv[NB], acco[NB];
    #pragma unroll
    for (int b=0;b<NB;b++){ accv[b]=0.f; acco[b]=0.f; }
    for (int e=0;e<NE;e++){
        float wv = w_v[(size_t)e*HC + j];
        float wo = o_w[(size_t)e*HC + j];
        #pragma unroll
        for (int b=0;b<NB;b++){
            float rr = r[b*NE+e];
            accv[b] = fmaf(rr, wv, accv[b]);
            acco[b] = fmaf(rr, wo, acco[b]);
        }
    }
    #pragma unroll
    for (int b=0;b<NB;b++){
        g_wv[(size_t)b*HC + j] = accv[b];
        g_wo[(size_t)b*HC + j] = acco[b];
    }
}

// ---------------- 3b) transpose Wv_eff (b,h,c) -> (b,c,h) ----------------
__global__ void k_trans(){
    __shared__ float ts[64][65];
    int b = blockIdx.y, c0 = blockIdx.x*64;
    int tid = threadIdx.x;  // 256
    int cc = tid & 63, q = tid >> 6;
    #pragma unroll
    for (int i=0;i<16;i++){
        int h = i*4 + q;
        ts[h][cc] = g_wv[(size_t)b*HC + (size_t)h*NC + c0 + cc];
    }
    __syncthreads();
    #pragma unroll
    for (int i=0;i<16;i++){
        int c = i*4 + q;
        g_wvT[(size_t)b*HC + (size_t)(c0+c)*NH + cc] = ts[cc][c];
    }
}

// ---------------- 4) GEMM1: g_comb2[ks] = X(:,kslice) @ WvT(kslice,:) ----------------
// block 256m x 64n, 256 threads, 8x8/thread, K=16 stages x32, double-buffered, 1 sync/stage
__global__ void __launch_bounds__(256, 2) k_gemm1(const float* __restrict__ X){
    __shared__ __align__(16) float4 As[2][4][256];   // 32KB
    __shared__ __align__(16) float  Bs[2][16][64];   //  8KB
    int tid = threadIdx.x;
    int mt = blockIdx.x, ks = blockIdx.y, b = blockIdx.z;
    const float* Ag = X     + ((size_t)(b*NT + mt*256))*NC + ks*512;
    const float* Bg = g_wvT + (size_t)b*HC + (size_t)(ks*512)*NH;
    int mi = tid & 31, ni = tid >> 5;
    int m0 = mi*8, n0 = ni*8;
    int am[4], akf4[4];
    #pragma unroll
    for (int i=0;i<4;i++){ int f = tid + i*256; am[i]=f>>2; akf4[i]=f&3; }
    int bk = tid >> 4, bn4 = tid & 15;

    ull acc[8][4];
    #pragma unroll
    for (int j=0;j<8;j++){
        #pragma unroll
        for (int p=0;p<4;p++) acc[j][p] = 0ull;
    }

    // prologue: stage 0
    #pragma unroll
    for (int i=0;i<4;i++){
        unsigned d = (unsigned)__cvta_generic_to_shared(&As[0][akf4[i]][swzA(akf4[i], am[i])]);
        CP_ASYNC16(d, Ag + (size_t)am[i]*NC + akf4[i]*4);
    }
    {
        unsigned d = (unsigned)__cvta_generic_to_shared(&Bs[0][bk][bn4*4]);
        CP_ASYNC16(d, Bg + (size_t)bk*NH + bn4*4);
    }
    CP_COMMIT();

    for (int t=0;t<32;t++){
        int buf = t & 1;
        CP_WAIT0();
        __syncthreads();
        if (t+1 < 32){
            int kb = (t+1)*16, nb = buf^1;
            #pragma unroll
            for (int i=0;i<4;i++){
                unsigned d = (unsigned)__cvta_generic_to_shared(&As[nb][akf4[i]][swzA(akf4[i], am[i])]);
                CP_ASYNC16(d, Ag + (size_t)am[i]*NC + kb + akf4[i]*4);
            }
            unsigned d = (unsigned)__cvta_generic_to_shared(&Bs[nb][bk][bn4*4]);
            CP_ASYNC16(d, Bg + (size_t)(kb + bk)*NH + bn4*4);
            CP_COMMIT();
        }
        #pragma unroll
        for (int kk=0;kk<4;kk++){
            float4 a4[8];
            #pragma unroll
            for (int j=0;j<8;j++) a4[j] = As[buf][kk][swzA(kk, m0+j)];
            #pragma unroll
            for (int dk=0;dk<4;dk++){
                const ulonglong2* bp = (const ulonglong2*)&Bs[buf][kk*4+dk][n0];
                ulonglong2 q0 = bp[0], q1 = bp[1];
                #pragma unroll
                for (int j=0;j<8;j++){
                    float a = fcomp(a4[j], dk);
                    ull aa = pk2(a, a);
                    fma2(acc[j][0], aa, q0.x); fma2(acc[j][1], aa, q0.y);
                    fma2(acc[j][2], aa, q1.x); fma2(acc[j][3], aa, q1.y);
                }
            }
        }
    }

    float* outp = g_comb2 + (size_t)ks*NROWS*NH;
    #pragma unroll
    for (int j=0;j<8;j++){
        size_t r = (size_t)(b*NT + mt*256 + m0 + j)*NH + n0;
        float2 c0 = upk2(acc[j][0]), c1 = upk2(acc[j][1]);
        float2 c2 = upk2(acc[j][2]), c3 = upk2(acc[j][3]);
        *(float4*)(outp + r)     = make_float4(c0.x, c0.y, c1.x, c1.y);
        *(float4*)(outp + r + 4) = make_float4(c2.x, c2.y, c3.x, c3.y);
    }
}

// ---------------- 5) GEMM2: out = (sum_ks comb2[ks]) @ Wo_eff  (K=64) ----------------
// block 128m x 128n, 256 threads, 8x8/thread; A one-shot (k-split summed at load), B 4 stages
__global__ void __launch_bounds__(256, 2) k_gemm2(float* __restrict__ out){
    __shared__ __align__(16) float4 As2[16][128];    // 32KB
    __shared__ __align__(16) float  Bs2[2][16][128]; // 16KB
    int tid = threadIdx.x;
    int nt = blockIdx.x, mt = blockIdx.y;
    int mbase = mt*128;
    int b = mbase / NT;
    int d0 = nt*128;
    const float* Bg = g_wo + (size_t)b*HC + d0;
    int mi = tid & 15, ni = tid >> 4;
    int m0 = mi*8, n0 = ni*8;

    // B stage 0
    #pragma unroll
    for (int i=0;i<2;i++){
        int f = tid + i*256; int k = f>>5, n4 = f&31;
        unsigned d = (unsigned)__cvta_generic_to_shared(&Bs2[0][k][n4*4]);
        CP_ASYNC16(d, Bg + (size_t)k*NC + n4*4);
    }
    CP_COMMIT();
    // A: sum the 4 k-split slices while loading (fused addcomb)
    const size_t st = (size_t)NROWS*NH;
    #pragma unroll
    for (int i=0;i<8;i++){
        int f = tid + i*256; int m = f>>4, kf4 = f&15;
        const float* p = g_comb2 + (size_t)(mbase+m)*NH + kf4*4;
        float4 v0 = *(const float4*)(p);
        float4 v1 = *(const float4*)(p + st);
        float4 v2 = *(const float4*)(p + 2*st);
        float4 v3 = *(const float4*)(p + 3*st);
        float4 s;
        s.x = (v0.x+v1.x)+(v2.x+v3.x); s.y = (v0.y+v1.y)+(v2.y+v3.y);
        s.z = (v0.z+v1.z)+(v2.z+v3.z); s.w = (v0.w+v1.w)+(v2.w+v3.w);
        As2[kf4][swzA(kf4, m)] = s;
    }

    ull acc[8][4];
    #pragma unroll
    for (int j=0;j<8;j++){
        #pragma unroll
        for (int p=0;p<4;p++) acc[j][p] = 0ull;
    }

    for (int s=0;s<4;s++){
        int buf = s & 1;
        CP_WAIT0();
        __syncthreads();
        if (s+1 < 4){
            int kb = (s+1)*16, nb = buf^1;
            #pragma unroll
            for (int i=0;i<2;i++){
                int f = tid + i*256; int k = f>>5, n4 = f&31;
                unsigned d = (unsigned)__cvta_generic_to_shared(&Bs2[nb][k][n4*4]);
                CP_ASYNC16(d, Bg + (size_t)(kb + k)*NC + n4*4);
            }
            CP_COMMIT();
        }
        #pragma unroll
        for (int kk=0;kk<4;kk++){
            int kf4 = s*4 + kk;
            float4 a4[8];
            #pragma unroll
            for (int j=0;j<8;j++) a4[j] = As2[kf4][swzA(kf4, m0+j)];
            #pragma unroll
            for (int dk=0;dk<4;dk++){
                const ulonglong2* bp = (const ulonglong2*)&Bs2[buf][kk*4+dk][n0];
                ulonglong2 q0 = bp[0], q1 = bp[1];
                #pragma unroll
                for (int j=0;j<8;j++){
                    float a = fcomp(a4[j], dk);
                    ull aa = pk2(a, a);
                    fma2(acc[j][0], aa, q0.x); fma2(acc[j][1], aa, q0.y);
                    fma2(acc[j][2], aa, q1.x); fma2(acc[j][3], aa, q1.y);
                }
            }
        }
    }

    #pragma unroll
    for (int j=0;j<8;j++){
        size_t r = (size_t)(mbase + m0 + j)*NC + d0 + n0;
        float2 c0 = upk2(acc[j][0]), c1 = upk2(acc[j][1]);
        float2 c2 = upk2(acc[j][2]), c3 = upk2(acc[j][3]);
        *(float4*)(out + r)     = make_float4(c0.x, c0.y, c1.x, c1.y);
        *(float4*)(out + r + 4) = make_float4(c2.x, c2.y, c3.x, c3.y);
    }
}

// ---------------- launch ----------------
extern "C" void kernel_launch(void* const* d_in, const int* in_sizes, int n_in,
                              void* d_out, int out_size){
    const float* X     = (const float*)d_in[0];
    const float* sim   = (const float*)d_in[1];
    const float* gates = (const float*)d_in[2];
    const float* w_v   = (const float*)d_in[5];
    const float* o_w   = (const float*)d_in[6];
    float* out = (float*)d_out;

    k_mean <<<dim3(NC/256, 16, NB), 256>>>(X);
    k_dots <<<NE + NB + NB*NE, 128>>>(sim);
    k_weff <<<HC/256, 256>>>(gates, w_v, o_w);
    k_trans<<<dim3(NC/64, NB), 256>>>();
    k_gemm1<<<dim3(NT/256, KSPLIT, NB), 256>>>(X);
    k_gemm2<<<dim3(NC/128, NROWS/128), 256>>>(out);
    (void)in_sizes; (void)n_in; (void)out_size;
}

// round 9
// speedup vs baseline: 1.6577x; 1.6577x over previous
#include <cuda_runtime.h>
#include <cuda_bf16.h>
#include <math.h>
#include <float.h>
#include <stdint.h>

#define NB 8
#define NT 2048
#define NC 2048
#define NE 32
#define NH 64
#define HC (NH*NC)
#define NROWS (NB*NT)

// ---------------- scratch (device globals; no allocation allowed) ----------------
__device__ __align__(16) float g_part[NB*16*NC];
__device__ float g_dots[NE + NB + NB*NE];
__device__ __align__(16) __nv_bfloat16 g_xhi[(size_t)NB*NT*NC];   // 64MiB
__device__ __align__(16) __nv_bfloat16 g_xlo[(size_t)NB*NT*NC];   // 64MiB
__device__ __align__(16) __nv_bfloat16 g_wvhi[NB*HC];             // Wv_eff hi (b,h,c)
__device__ __align__(16) __nv_bfloat16 g_wvlo[NB*HC];
__device__ __align__(16) float g_wo[NB*HC];                       // Wo_eff fp32 (b,h,c)
__device__ __align__(16) __nv_bfloat16 g_wothi[NB*HC];            // Wo_eff^T hi (b,d,h)
__device__ __align__(16) __nv_bfloat16 g_wotlo[NB*HC];
__device__ __align__(16) __nv_bfloat16 g_chi[(size_t)NROWS*NH];   // comb hi (row,h)
__device__ __align__(16) __nv_bfloat16 g_clo[(size_t)NROWS*NH];

// ---------------- helpers ----------------
__device__ __forceinline__ uint32_t smem_u32(const void* p){
    uint32_t a;
    asm("{ .reg .u64 t; cvta.to.shared.u64 t, %1; cvt.u32.u64 %0, t; }" : "=r"(a) : "l"(p));
    return a;
}
#define SWZ(x) ((x) ^ (((x)>>3)&0x70))
#define CPA16(dst,src) asm volatile("cp.async.cg.shared.global [%0], [%1], 16;" :: "r"(dst), "l"(src))
#define CPC() asm volatile("cp.async.commit_group;")
#define CPW1() asm volatile("cp.async.wait_group 1;")
#define CPW0() asm volatile("cp.async.wait_group 0;")

__device__ __forceinline__ void ldsm_x4(uint32_t a, uint32_t& r0, uint32_t& r1, uint32_t& r2, uint32_t& r3){
    asm volatile("ldmatrix.sync.aligned.m8n8.x4.shared.b16 {%0,%1,%2,%3}, [%4];"
        : "=r"(r0),"=r"(r1),"=r"(r2),"=r"(r3) : "r"(a));
}
__device__ __forceinline__ void mma_bf16(float* c, uint32_t a0,uint32_t a1,uint32_t a2,uint32_t a3,
                                         uint32_t b0,uint32_t b1){
    asm volatile("mma.sync.aligned.m16n8k16.row.col.f32.bf16.bf16.f32 "
        "{%0,%1,%2,%3}, {%4,%5,%6,%7}, {%8,%9}, {%0,%1,%2,%3};"
        : "+f"(c[0]),"+f"(c[1]),"+f"(c[2]),"+f"(c[3])
        : "r"(a0),"r"(a1),"r"(a2),"r"(a3),"r"(b0),"r"(b1));
}
__device__ __forceinline__ float wredsum(float v){
    #pragma unroll
    for (int o=16;o>0;o>>=1) v += __shfl_xor_sync(0xffffffffu, v, o);
    return v;
}
__device__ __forceinline__ float wredmax(float v){
    #pragma unroll
    for (int o=16;o>0;o>>=1) v = fmaxf(v, __shfl_xor_sync(0xffffffffu, v, o));
    return v;
}
__device__ __forceinline__ void split_bf16(float f, __nv_bfloat16& h, __nv_bfloat16& l){
    h = __float2bfloat16(f);
    l = __float2bfloat16(f - __bfloat162float(h));
}

// ---------------- 1) X pass: column sums + hi/lo split ----------------
__global__ void k_splitmean(const float* __restrict__ X){
    int c = blockIdx.x*256 + threadIdx.x;
    int s = blockIdx.y, b = blockIdx.z;
    size_t base = ((size_t)b*NT + (size_t)s*128)*NC + c;
    const float* p = X + base;
    __nv_bfloat16* ph = g_xhi + base;
    __nv_bfloat16* pl = g_xlo + base;
    float acc = 0.f;
    #pragma unroll 4
    for (int t=0;t<128;t++){
        float f = p[(size_t)t*NC];
        acc += f;
        __nv_bfloat16 h, l;
        split_bf16(f, h, l);
        ph[(size_t)t*NC] = h;
        pl[(size_t)t*NC] = l;
    }
    g_part[(b*16+s)*NC + c] = acc;
}

// ---------------- 2) norms + affinity dots ----------------
__global__ void k_dots(const float* __restrict__ sim){
    __shared__ float sred[4];
    int task = blockIdx.x;
    int tid = threadIdx.x;
    float acc = 0.f;
    if (task < NE){
        int e = task;
        for (int c = tid; c < NC; c += 128){ float v = sim[c*NE + e]; acc += v*v; }
    } else if (task < NE+NB){
        int b = task - NE;
        for (int c = tid; c < NC; c += 128){
            float v = 0.f;
            #pragma unroll
            for (int s=0;s<16;s++) v += g_part[(b*16+s)*NC + c];
            acc += v*v;
        }
    } else {
        int p = task - NE - NB;
        int b = p >> 5, e = p & 31;
        for (int c = tid; c < NC; c += 128){
            float v = 0.f;
            #pragma unroll
            for (int s=0;s<16;s++) v += g_part[(b*16+s)*NC + c];
            acc += v * sim[c*NE + e];
        }
    }
    acc = wredsum(acc);
    if ((tid & 31) == 0) sred[tid>>5] = acc;
    __syncthreads();
    if (tid == 0) g_dots[task] = (sred[0]+sred[1])+(sred[2]+sred[3]);
}

// ---------------- 3) gating + fold; Wv split to bf16, Wo kept fp32 ----------------
__global__ void k_weff(const float* __restrict__ gates,
                       const float* __restrict__ w_v, const float* __restrict__ o_w){
    __shared__ float r[NB*NE];
    int tid = threadIdx.x;
    {
        int lane = tid & 31, b = tid >> 5;
        float nsim2 = g_dots[lane];
        float nseq2 = g_dots[NE + b];
        float dot   = g_dots[NE + NB + b*NE + lane];
        float aff = dot / sqrtf(nsim2 * nseq2);
        float sig = 1.f / (1.f + expf(-gates[lane]));
        float logit = aff - sig;
        float gated = fmaxf(logit, 0.f);
        bool  act = gated > 0.f;
        unsigned actm = __ballot_sync(0xffffffffu, act);
        bool use = act;
        if (actm == 0u){
            int rank = 0;
            #pragma unroll
            for (int e=0;e<NE;e++){
                float le = __shfl_sync(0xffffffffu, logit, e);
                rank += (le > logit) || (le == logit && e < lane);
            }
            use = rank < 16;
        }
        float v = use ? gated : -FLT_MAX;
        float mx = wredmax(v);
        float ex = use ? expf(gated - mx) : 0.f;
        float sm = wredsum(ex);
        r[tid] = ex / sm;
    }
    __syncthreads();
    int j = blockIdx.x*256 + tid;
    float accv[NB], acco[NB];
    #pragma unroll
    for (int b=0;b<NB;b++){ accv[b]=0.f; acco[b]=0.f; }
    for (int e=0;e<NE;e++){
        float wv = w_v[(size_t)e*HC + j];
        float wo = o_w[(size_t)e*HC + j];
        #pragma unroll
        for (int b=0;b<NB;b++){
            float rr = r[b*NE+e];
            accv[b] = fmaf(rr, wv, accv[b]);
            acco[b] = fmaf(rr, wo, acco[b]);
        }
    }
    #pragma unroll
    for (int b=0;b<NB;b++){
        __nv_bfloat16 h, l;
        split_bf16(accv[b], h, l);
        g_wvhi[(size_t)b*HC + j] = h;
        g_wvlo[(size_t)b*HC + j] = l;
        g_wo[(size_t)b*HC + j] = acco[b];
    }
}

// ---------------- 3b) transpose+split Wo_eff (b,h,d) -> (b,d,h) bf16 hi/lo ----------------
__global__ void k_trans2(){
    __shared__ float ts[64][65];
    int b = blockIdx.y, d0 = blockIdx.x*64;
    int tid = threadIdx.x;
    int cc = tid & 63, q = tid >> 6;
    #pragma unroll
    for (int i=0;i<16;i++){
        int h = i*4 + q;
        ts[h][cc] = g_wo[(size_t)b*HC + (size_t)h*NC + d0 + cc];
    }
    __syncthreads();
    #pragma unroll
    for (int i=0;i<16;i++){
        int d = i*4 + q;
        float f = ts[cc][d];
        __nv_bfloat16 h, l;
        split_bf16(f, h, l);
        size_t o = (size_t)b*HC + (size_t)(d0+d)*NH + cc;
        g_wothi[o] = h;
        g_wotlo[o] = l;
    }
}

// ---------------- GEMM1 smem layout: 3 stages x 48KB ----------------
#define G1_STG   49152
#define G1_A_HI  0
#define G1_A_LO  16384
#define G1_B_HI  32768
#define G1_B_LO  40960
#define G1_SMEM  (3*G1_STG)

__device__ __forceinline__ void g1_load(uint32_t stg,
        const __nv_bfloat16* xh, const __nv_bfloat16* xl,
        const __nv_bfloat16* bh, const __nv_bfloat16* bl, int ck, int tid){
    int c0 = ck*64;
    #pragma unroll
    for (int i=0;i<8;i++){
        int u = tid + i*256;
        int sel = u>>10, w = u & 1023;
        int row = w>>3, seg = w&7;
        uint32_t dst = stg + (sel?G1_A_LO:G1_A_HI) + SWZ(row*128 + seg*16);
        CPA16(dst, (sel?xl:xh) + (size_t)row*NC + c0 + seg*8);
    }
    #pragma unroll
    for (int i=0;i<4;i++){
        int u = tid + i*256;
        int sel = u>>9, w = u & 511;
        int row = w>>3, seg = w&7;
        uint32_t dst = stg + (sel?G1_B_LO:G1_B_HI) + SWZ(row*128 + seg*16);
        CPA16(dst, (sel?bl:bh) + (size_t)row*NC + c0 + seg*8);
    }
    CPC();
}

// ---------------- 4) GEMM1: comb = X @ Wv_eff^T (split bf16, HMMA) ----------------
__global__ void __launch_bounds__(256, 1) k_gemm1_tc(){
    extern __shared__ __align__(1024) char sm1[];
    uint32_t sb = smem_u32(sm1);
    int tid = threadIdx.x;
    int wid = tid >> 5, lid = tid & 31;
    int wm = wid & 3, wn = wid >> 2;            // warp grid 4(M) x 2(N), warp tile 32x32
    int mt0 = blockIdx.x, b = blockIdx.y;
    int t0 = mt0*128;

    const __nv_bfloat16* xh = g_xhi + ((size_t)(b*NT + t0))*NC;
    const __nv_bfloat16* xl = g_xlo + ((size_t)(b*NT + t0))*NC;
    const __nv_bfloat16* bh = g_wvhi + (size_t)b*HC;
    const __nv_bfloat16* bl = g_wvlo + (size_t)b*HC;

    float acc[2][4][4];
    #pragma unroll
    for (int mt=0;mt<2;mt++)
        #pragma unroll
        for (int nt=0;nt<4;nt++)
            #pragma unroll
            for (int q=0;q<4;q++) acc[mt][nt][q] = 0.f;

    g1_load(sb + 0*G1_STG, xh, xl, bh, bl, 0, tid);
    g1_load(sb + 1*G1_STG, xh, xl, bh, bl, 1, tid);

    for (int t=0;t<32;t++){
        if (t < 31) { CPW1(); } else { CPW0(); }
        __syncthreads();
        if (t+2 < 32) g1_load(sb + ((t+2)%3)*G1_STG, xh, xl, bh, bl, t+2, tid);
        uint32_t stg = sb + (t%3)*G1_STG;
        #pragma unroll
        for (int kk=0;kk<4;kk++){
            uint32_t ah[2][4], al[2][4], bhf[4][2], blf[4][2];
            #pragma unroll
            for (int mt=0;mt<2;mt++){
                int row = wm*32 + mt*16 + (lid&15);
                uint32_t off = SWZ(row*128 + kk*32 + (lid>>4)*16);
                ldsm_x4(stg + G1_A_HI + off, ah[mt][0],ah[mt][1],ah[mt][2],ah[mt][3]);
                ldsm_x4(stg + G1_A_LO + off, al[mt][0],al[mt][1],al[mt][2],al[mt][3]);
            }
            #pragma unroll
            for (int ng=0;ng<2;ng++){
                int row = wn*32 + ng*16 + (lid&7) + ((lid>>4)<<3);
                uint32_t off = SWZ(row*128 + kk*32 + ((lid>>3)&1)*16);
                ldsm_x4(stg + G1_B_HI + off, bhf[2*ng][0], bhf[2*ng][1], bhf[2*ng+1][0], bhf[2*ng+1][1]);
                ldsm_x4(stg + G1_B_LO + off, blf[2*ng][0], blf[2*ng][1], blf[2*ng+1][0], blf[2*ng+1][1]);
            }
            #pragma unroll
            for (int mt=0;mt<2;mt++){
                #pragma unroll
                for (int nt=0;nt<4;nt++){
                    mma_bf16(acc[mt][nt], ah[mt][0],ah[mt][1],ah[mt][2],ah[mt][3], bhf[nt][0],bhf[nt][1]);
                    mma_bf16(acc[mt][nt], ah[mt][0],ah[mt][1],ah[mt][2],ah[mt][3], blf[nt][0],blf[nt][1]);
                    mma_bf16(acc[mt][nt], al[mt][0],al[mt][1],al[mt][2],al[mt][3], bhf[nt][0],bhf[nt][1]);
                }
            }
        }
    }

    // epilogue: split acc -> g_chi/g_clo (row-major [row][64])
    #pragma unroll
    for (int mt=0;mt<2;mt++){
        #pragma unroll
        for (int nt=0;nt<4;nt++){
            float* c = acc[mt][nt];
            int row = b*NT + t0 + wm*32 + mt*16 + (lid>>2);
            int col = wn*32 + nt*8 + (lid&3)*2;
            #pragma unroll
            for (int h2=0;h2<2;h2++){
                int rr = row + h2*8;
                float fa = c[2*h2], fb = c[2*h2+1];
                __nv_bfloat16 ha, la, hb2, lb2;
                split_bf16(fa, ha, la);
                split_bf16(fb, hb2, lb2);
                uint32_t uh = (uint32_t)__bfloat16_as_ushort(ha) | ((uint32_t)__bfloat16_as_ushort(hb2)<<16);
                uint32_t ul = (uint32_t)__bfloat16_as_ushort(la) | ((uint32_t)__bfloat16_as_ushort(lb2)<<16);
                *(uint32_t*)(g_chi + (size_t)rr*NH + col) = uh;
                *(uint32_t*)(g_clo + (size_t)rr*NH + col) = ul;
            }
        }
    }
}

// ---------------- GEMM2 smem layout: 64KB single shot ----------------
#define G2_A_HI  0
#define G2_A_LO  16384
#define G2_B_HI  32768
#define G2_B_LO  49152
#define G2_SMEM  65536

// ---------------- 5) GEMM2: out = comb @ Wo_eff (split bf16, HMMA) ----------------
__global__ void __launch_bounds__(256, 1) k_gemm2_tc(float* __restrict__ out){
    extern __shared__ __align__(1024) char sm2[];
    uint32_t sb = smem_u32(sm2);
    int tid = threadIdx.x;
    int wid = tid >> 5, lid = tid & 31;
    int wm = wid & 3, wn = wid >> 2;            // warp tile 32m x 64n
    int nt0 = blockIdx.x, mt0 = blockIdx.y;
    int mbase = mt0*128;
    int b = mbase / NT;
    int d0 = nt0*128;

    const __nv_bfloat16* ah = g_chi + (size_t)mbase*NH;
    const __nv_bfloat16* al = g_clo + (size_t)mbase*NH;
    const __nv_bfloat16* bh = g_wothi + (size_t)b*HC + (size_t)d0*NH;
    const __nv_bfloat16* bl = g_wotlo + (size_t)b*HC + (size_t)d0*NH;

    #pragma unroll
    for (int i=0;i<16;i++){
        int u = tid + i*256;
        int sel = u>>10, w = u & 1023;
        int row = w>>3, seg = w&7;
        uint32_t off = SWZ(row*128 + seg*16);
        const __nv_bfloat16* src = (sel==0?ah:(sel==1?al:(sel==2?bh:bl))) + (size_t)row*NH + seg*8;
        uint32_t base = (sel==0?G2_A_HI:(sel==1?G2_A_LO:(sel==2?G2_B_HI:G2_B_LO)));
        CPA16(sb + base + off, src);
    }
    CPC();
    CPW0();
    __syncthreads();

    float acc[2][8][4];
    #pragma unroll
    for (int mt=0;mt<2;mt++)
        #pragma unroll
        for (int nt=0;nt<8;nt++)
            #pragma unroll
            for (int q=0;q<4;q++) acc[mt][nt][q] = 0.f;

    #pragma unroll
    for (int kk=0;kk<4;kk++){
        uint32_t ahf[2][4], alf[2][4], bhf[8][2], blf[8][2];
        #pragma unroll
        for (int mt=0;mt<2;mt++){
            int row = wm*32 + mt*16 + (lid&15);
            uint32_t off = SWZ(row*128 + kk*32 + (lid>>4)*16);
            ldsm_x4(sb + G2_A_HI + off, ahf[mt][0],ahf[mt][1],ahf[mt][2],ahf[mt][3]);
            ldsm_x4(sb + G2_A_LO + off, alf[mt][0],alf[mt][1],alf[mt][2],alf[mt][3]);
        }
        #pragma unroll
        for (int ng=0;ng<4;ng++){
            int row = wn*64 + ng*16 + (lid&7) + ((lid>>4)<<3);
            uint32_t off = SWZ(row*128 + kk*32 + ((lid>>3)&1)*16);
            ldsm_x4(sb + G2_B_HI + off, bhf[2*ng][0], bhf[2*ng][1], bhf[2*ng+1][0], bhf[2*ng+1][1]);
            ldsm_x4(sb + G2_B_LO + off, blf[2*ng][0], blf[2*ng][1], blf[2*ng+1][0], blf[2*ng+1][1]);
        }
        #pragma unroll
        for (int mt=0;mt<2;mt++){
            #pragma unroll
            for (int nt=0;nt<8;nt++){
                mma_bf16(acc[mt][nt], ahf[mt][0],ahf[mt][1],ahf[mt][2],ahf[mt][3], bhf[nt][0],bhf[nt][1]);
                mma_bf16(acc[mt][nt], ahf[mt][0],ahf[mt][1],ahf[mt][2],ahf[mt][3], blf[nt][0],blf[nt][1]);
                mma_bf16(acc[mt][nt], alf[mt][0],alf[mt][1],alf[mt][2],alf[mt][3], bhf[nt][0],bhf[nt][1]);
            }
        }
    }

    #pragma unroll
    for (int mt=0;mt<2;mt++){
        #pragma unroll
        for (int nt=0;nt<8;nt++){
            float* c = acc[mt][nt];
            int row = mbase + wm*32 + mt*16 + (lid>>2);
            int col = d0 + wn*64 + nt*8 + (lid&3)*2;
            *(float2*)(out + (size_t)row*NC + col)       = make_float2(c[0], c[1]);
            *(float2*)(out + (size_t)(row+8)*NC + col)   = make_float2(c[2], c[3]);
        }
    }
}

// ---------------- launch ----------------
extern "C" void kernel_launch(void* const* d_in, const int* in_sizes, int n_in,
                              void* d_out, int out_size){
    const float* X     = (const float*)d_in[0];
    const float* sim   = (const float*)d_in[1];
    const float* gates = (const float*)d_in[2];
    const float* w_v   = (const float*)d_in[5];
    const float* o_w   = (const float*)d_in[6];
    float* out = (float*)d_out;

    static int attr_done = 0;
    if (!attr_done){
        cudaFuncSetAttribute(k_gemm1_tc, cudaFuncAttributeMaxDynamicSharedMemorySize, G1_SMEM);
        cudaFuncSetAttribute(k_gemm2_tc, cudaFuncAttributeMaxDynamicSharedMemorySize, G2_SMEM);
        attr_done = 1;
    }

    k_splitmean<<<dim3(NC/256, 16, NB), 256>>>(X);
    k_dots     <<<NE + NB + NB*NE, 128>>>(sim);
    k_weff     <<<HC/256, 256>>>(gates, w_v, o_w);
    k_trans2   <<<dim3(NC/64, NB), 256>>>();
    k_gemm1_tc <<<dim3(NT/128, NB), 256, G1_SMEM>>>();
    k_gemm2_tc <<<dim3(NC/128, NROWS/128), 256, G2_SMEM>>>(out);
    (void)in_sizes; (void)n_in; (void)out_size;
}

// round 11
// speedup vs baseline: 1.7146x; 1.0343x over previous
#include <cuda_runtime.h>
#include <cuda_bf16.h>
#include <math.h>
#include <float.h>
#include <stdint.h>

#define NB 8
#define NT 2048
#define NC 2048
#define NE 32
#define NH 64
#define HC (NH*NC)
#define NROWS (NB*NT)

// ---------------- scratch (device globals; no allocation allowed) ----------------
__device__ __align__(16) float g_part[NB*16*NC];
__device__ float g_dots[NE + NB + NB*NE];
__device__ __align__(16) __nv_bfloat16 g_wvhi[NB*HC];             // Wv_eff hi (b,h,c)
__device__ __align__(16) __nv_bfloat16 g_wvlo[NB*HC];
__device__ __align__(16) float g_wo[NB*HC];                       // Wo_eff fp32 (b,h,c)
__device__ __align__(16) __nv_bfloat16 g_wothi[NB*HC];            // Wo_eff^T hi (b,d,h)
__device__ __align__(16) __nv_bfloat16 g_wotlo[NB*HC];
__device__ __align__(16) __nv_bfloat16 g_chi[(size_t)NROWS*NH];   // comb hi (row,h)
__device__ __align__(16) __nv_bfloat16 g_clo[(size_t)NROWS*NH];

// ---------------- helpers ----------------
__device__ __forceinline__ uint32_t smem_u32(const void* p){
    uint32_t a;
    asm("{ .reg .u64 t; cvta.to.shared.u64 t, %1; cvt.u32.u64 %0, t; }" : "=r"(a) : "l"(p));
    return a;
}
#define SWZ(x) ((x) ^ (((x)>>3)&0x70))
#define CPA16(dst,src) asm volatile("cp.async.cg.shared.global [%0], [%1], 16;" :: "r"(dst), "l"(src))
#define CPC() asm volatile("cp.async.commit_group;")
#define CPW1() asm volatile("cp.async.wait_group 1;")
#define CPW0() asm volatile("cp.async.wait_group 0;")

__device__ __forceinline__ void ldsm_x4(uint32_t a, uint32_t& r0, uint32_t& r1, uint32_t& r2, uint32_t& r3){
    asm volatile("ldmatrix.sync.aligned.m8n8.x4.shared.b16 {%0,%1,%2,%3}, [%4];"
        : "=r"(r0),"=r"(r1),"=r"(r2),"=r"(r3) : "r"(a));
}
__device__ __forceinline__ float2 lds64(uint32_t a){
    float2 f;
    asm volatile("ld.shared.v2.f32 {%0,%1}, [%2];" : "=f"(f.x), "=f"(f.y) : "r"(a));
    return f;
}
__device__ __forceinline__ void mma_bf16(float* c, uint32_t a0,uint32_t a1,uint32_t a2,uint32_t a3,
                                         uint32_t b0,uint32_t b1){
    asm volatile("mma.sync.aligned.m16n8k16.row.col.f32.bf16.bf16.f32 "
        "{%0,%1,%2,%3}, {%4,%5,%6,%7}, {%8,%9}, {%0,%1,%2,%3};"
        : "+f"(c[0]),"+f"(c[1]),"+f"(c[2]),"+f"(c[3])
        : "r"(a0),"r"(a1),"r"(a2),"r"(a3),"r"(b0),"r"(b1));
}
__device__ __forceinline__ float wredsum(float v){
    #pragma unroll
    for (int o=16;o>0;o>>=1) v += __shfl_xor_sync(0xffffffffu, v, o);
    return v;
}
__device__ __forceinline__ float wredmax(float v){
    #pragma unroll
    for (int o=16;o>0;o>>=1) v = fmaxf(v, __shfl_xor_sync(0xffffffffu, v, o));
    return v;
}
__device__ __forceinline__ void split_bf16(float f, __nv_bfloat16& h, __nv_bfloat16& l){
    h = __float2bfloat16(f);
    l = __float2bfloat16(f - __bfloat162float(h));
}
// split an fp32 pair into packed bf16x2 hi and lo fragments
__device__ __forceinline__ void splitpack2(float2 f, uint32_t& hi, uint32_t& lo){
    __nv_bfloat16 h0 = __float2bfloat16(f.x), h1 = __float2bfloat16(f.y);
    __nv_bfloat16 l0 = __float2bfloat16(f.x - __bfloat162float(h0));
    __nv_bfloat16 l1 = __float2bfloat16(f.y - __bfloat162float(h1));
    hi = (uint32_t)__bfloat16_as_ushort(h0) | ((uint32_t)__bfloat16_as_ushort(h1) << 16);
    lo = (uint32_t)__bfloat16_as_ushort(l0) | ((uint32_t)__bfloat16_as_ushort(l1) << 16);
}

// ---------------- 1) mean pass: column sums only ----------------
__global__ void k_mean(const float* __restrict__ X){
    int c = blockIdx.x*256 + threadIdx.x;
    int s = blockIdx.y, b = blockIdx.z;
    const float* p = X + ((size_t)b*NT + (size_t)s*128)*NC + c;
    float a0=0.f,a1=0.f,a2=0.f,a3=0.f;
    for (int t=0;t<128;t+=4){
        a0 += p[0]; a1 += p[NC]; a2 += p[2*NC]; a3 += p[3*NC];
        p += (size_t)4*NC;
    }
    g_part[(b*16+s)*NC + c] = (a0+a1)+(a2+a3);
}

// ---------------- 2) norms + affinity dots ----------------
__global__ void k_dots(const float* __restrict__ sim){
    __shared__ float sred[4];
    int task = blockIdx.x;
    int tid = threadIdx.x;
    float acc = 0.f;
    if (task < NE){
        int e = task;
        for (int c = tid; c < NC; c += 128){ float v = sim[c*NE + e]; acc += v*v; }
    } else if (task < NE+NB){
        int b = task - NE;
        for (int c = tid; c < NC; c += 128){
            float v = 0.f;
            #pragma unroll
            for (int s=0;s<16;s++) v += g_part[(b*16+s)*NC + c];
            acc += v*v;
        }
    } else {
        int p = task - NE - NB;
        int b = p >> 5, e = p & 31;
        for (int c = tid; c < NC; c += 128){
            float v = 0.f;
            #pragma unroll
            for (int s=0;s<16;s++) v += g_part[(b*16+s)*NC + c];
            acc += v * sim[c*NE + e];
        }
    }
    acc = wredsum(acc);
    if ((tid & 31) == 0) sred[tid>>5] = acc;
    __syncthreads();
    if (tid == 0) g_dots[task] = (sred[0]+sred[1])+(sred[2]+sred[3]);
}

// ---------------- 3) gating + fold; Wv split to bf16, Wo kept fp32 ----------------
__global__ void k_weff(const float* __restrict__ gates,
                       const float* __restrict__ w_v, const float* __restrict__ o_w){
    __shared__ float r[NB*NE];
    int tid = threadIdx.x;
    {
        int lane = tid & 31, b = tid >> 5;
        float nsim2 = g_dots[lane];
        float nseq2 = g_dots[NE + b];
        float dot   = g_dots[NE + NB + b*NE + lane];
        float aff = dot / sqrtf(nsim2 * nseq2);
        float sig = 1.f / (1.f + expf(-gates[lane]));
        float logit = aff - sig;
        float gated = fmaxf(logit, 0.f);
        bool  act = gated > 0.f;
        unsigned actm = __ballot_sync(0xffffffffu, act);
        bool use = act;
        if (actm == 0u){
            int rank = 0;
            #pragma unroll
            for (int e=0;e<NE;e++){
                float le = __shfl_sync(0xffffffffu, logit, e);
                rank += (le > logit) || (le == logit && e < lane);
            }
            use = rank < 16;
        }
        float v = use ? gated : -FLT_MAX;
        float mx = wredmax(v);
        float ex = use ? expf(gated - mx) : 0.f;
        float sm = wredsum(ex);
        r[tid] = ex / sm;
    }
    __syncthreads();
    int j = blockIdx.x*256 + tid;
    float accv[NB], acco[NB];
    #pragma unroll
    for (int b=0;b<NB;b++){ accv[b]=0.f; acco[b]=0.f; }
    for (int e=0;e<NE;e++){
        float wv = w_v[(size_t)e*HC + j];
        float wo = o_w[(size_t)e*HC + j];
        #pragma unroll
        for (int b=0;b<NB;b++){
            float rr = r[b*NE+e];
            accv[b] = fmaf(rr, wv, accv[b]);
            acco[b] = fmaf(rr, wo, acco[b]);
        }
    }
    #pragma unroll
    for (int b=0;b<NB;b++){
        __nv_bfloat16 h, l;
        split_bf16(accv[b], h, l);
        g_wvhi[(size_t)b*HC + j] = h;
        g_wvlo[(size_t)b*HC + j] = l;
        g_wo[(size_t)b*HC + j] = acco[b];
    }
}

// ---------------- 3b) transpose+split Wo_eff (b,h,d) -> (b,d,h) bf16 hi/lo ----------------
__global__ void k_trans2(){
    __shared__ float ts[64][65];
    int b = blockIdx.y, d0 = blockIdx.x*64;
    int tid = threadIdx.x;
    int cc = tid & 63, q = tid >> 6;
    #pragma unroll
    for (int i=0;i<16;i++){
        int h = i*4 + q;
        ts[h][cc] = g_wo[(size_t)b*HC + (size_t)h*NC + d0 + cc];
    }
    __syncthreads();
    #pragma unroll
    for (int i=0;i<16;i++){
        int d = i*4 + q;
        float f = ts[cc][d];
        __nv_bfloat16 h, l;
        split_bf16(f, h, l);
        size_t o = (size_t)b*HC + (size_t)(d0+d)*NH + cc;
        g_wothi[o] = h;
        g_wotlo[o] = l;
    }
}

// ---------------- GEMM1 smem: 3 stages x 32KB (A fp32 16KB + B hi 8KB + B lo 8KB) ----------------
#define G1_A     0
#define G1_B_HI  16384
#define G1_B_LO  24576
#define G1_STG   32768
#define G1_SMEM  (3*G1_STG)

// A tile stored as 128 half-rows (srow = row*2 + k/32) of 32 fp32 (128B), SW128 swizzled
__device__ __forceinline__ uint32_t a_addr(uint32_t base, int row, int k){
    int srow = row*2 + (k>>5);
    int kin = k & 31;
    return base + srow*128 + (((kin>>2) ^ (srow&7))*16) + (kin&3)*4;
}

__device__ __forceinline__ void g1_load(uint32_t stg, const float* X4,
        const __nv_bfloat16* bh, const __nv_bfloat16* bl, int ck, int tid){
    int c0 = ck*64;
    // A: 64 rows x 64 fp32 = 1024 x 16B granules
    #pragma unroll
    for (int i=0;i<4;i++){
        int u = tid + i*256;
        int row = u>>4, g = u&15;
        int srow = row*2 + (g>>3);
        uint32_t dst = stg + G1_A + srow*128 + (((g&7) ^ (srow&7))*16);
        CPA16(dst, X4 + (size_t)row*NC + c0 + g*4);
    }
    // B: hi/lo 64n x 64k bf16 = 512 granules each
    #pragma unroll
    for (int i=0;i<4;i++){
        int u = tid + i*256;
        int sel = u>>9, w = u&511;
        int n = w>>3, seg = w&7;
        uint32_t dst = stg + (sel?G1_B_LO:G1_B_HI) + SWZ(n*128 + seg*16);
        CPA16(dst, (sel?bl:bh) + (size_t)n*NC + c0 + seg*8);
    }
    CPC();
}

// ---------------- 4) GEMM1: comb = X @ Wv_eff^T (in-register split, HMMA) ----------------
// block tile 64m x 64n, 256 threads, warp grid 4m x 2n, warp tile 16m x 32n
__global__ void __launch_bounds__(256, 2) k_gemm1_tc(const float* __restrict__ X){
    extern __shared__ __align__(1024) char sm1[];
    uint32_t sb = smem_u32(sm1);
    int tid = threadIdx.x;
    int wid = tid >> 5, lid = tid & 31;
    int wm = wid & 3, wn = wid >> 2;
    int mt0 = blockIdx.x, b = blockIdx.y;
    int t0 = mt0*64;

    const float* Xg = X + ((size_t)(b*NT + t0))*NC;
    const __nv_bfloat16* bh = g_wvhi + (size_t)b*HC;
    const __nv_bfloat16* bl = g_wvlo + (size_t)b*HC;

    float acc[4][4];
    #pragma unroll
    for (int nt=0;nt<4;nt++)
        #pragma unroll
        for (int q=0;q<4;q++) acc[nt][q] = 0.f;

    g1_load(sb + 0*G1_STG, Xg, bh, bl, 0, tid);
    g1_load(sb + 1*G1_STG, Xg, bh, bl, 1, tid);

    int ar = wm*16 + (lid>>2);     // A row within tile
    int akc = (lid&3)*2;           // A col base within k16

    for (int t=0;t<32;t++){
        if (t < 31) { CPW1(); } else { CPW0(); }
        __syncthreads();
        if (t+2 < 32) g1_load(sb + ((t+2)%3)*G1_STG, Xg, bh, bl, t+2, tid);
        uint32_t stg = sb + (t%3)*G1_STG;
        #pragma unroll
        for (int kk=0;kk<4;kk++){
            int kb = kk*16 + akc;
            // A fragments: hi and lo built in registers from fp32 smem
            uint32_t ah[4], al[4];
            {
                float2 p0 = lds64(a_addr(stg + G1_A, ar,   kb));
                float2 p1 = lds64(a_addr(stg + G1_A, ar+8, kb));
                float2 p2 = lds64(a_addr(stg + G1_A, ar,   kb+8));
                float2 p3 = lds64(a_addr(stg + G1_A, ar+8, kb+8));
                splitpack2(p0, ah[0], al[0]);
                splitpack2(p1, ah[1], al[1]);
                splitpack2(p2, ah[2], al[2]);
                splitpack2(p3, ah[3], al[3]);
            }
            uint32_t bhf[4][2], blf[4][2];
            #pragma unroll
            for (int ng=0;ng<2;ng++){
                int row = wn*32 + ng*16 + (lid&7) + ((lid>>4)<<3);
                uint32_t off = SWZ(row*128 + kk*32 + ((lid>>3)&1)*16);
                ldsm_x4(stg + G1_B_HI + off, bhf[2*ng][0], bhf[2*ng][1], bhf[2*ng+1][0], bhf[2*ng+1][1]);
                ldsm_x4(stg + G1_B_LO + off, blf[2*ng][0], blf[2*ng][1], blf[2*ng+1][0], blf[2*ng+1][1]);
            }
            #pragma unroll
            for (int nt=0;nt<4;nt++){
                mma_bf16(acc[nt], ah[0],ah[1],ah[2],ah[3], bhf[nt][0],bhf[nt][1]);
                mma_bf16(acc[nt], ah[0],ah[1],ah[2],ah[3], blf[nt][0],blf[nt][1]);
                mma_bf16(acc[nt], al[0],al[1],al[2],al[3], bhf[nt][0],bhf[nt][1]);
            }
        }
    }

    // epilogue: split acc -> g_chi/g_clo
    #pragma unroll
    for (int nt=0;nt<4;nt++){
        float* c = acc[nt];
        int row = b*NT + t0 + wm*16 + (lid>>2);
        int col = wn*32 + nt*8 + (lid&3)*2;
        #pragma unroll
        for (int h2=0;h2<2;h2++){
            int rr = row + h2*8;
            float fa = c[2*h2], fb = c[2*h2+1];
            __nv_bfloat16 ha, la, hb2, lb2;
            split_bf16(fa, ha, la);
            split_bf16(fb, hb2, lb2);
            uint32_t uh = (uint32_t)__bfloat16_as_ushort(ha) | ((uint32_t)__bfloat16_as_ushort(hb2)<<16);
            uint32_t ul = (uint32_t)__bfloat16_as_ushort(la) | ((uint32_t)__bfloat16_as_ushort(lb2)<<16);
            *(uint32_t*)(g_chi + (size_t)rr*NH + col) = uh;
            *(uint32_t*)(g_clo + (size_t)rr*NH + col) = ul;
        }
    }
}

// ---------------- GEMM2 smem layout: 64KB single shot ----------------
#define G2_A_HI  0
#define G2_A_LO  16384
#define G2_B_HI  32768
#define G2_B_LO  49152
#define G2_SMEM  65536

// ---------------- 5) GEMM2: out = comb @ Wo_eff (split bf16, HMMA) ----------------
__global__ void __launch_bounds__(256, 1) k_gemm2_tc(float* __restrict__ out){
    extern __shared__ __align__(1024) char sm2[];
    uint32_t sb = smem_u32(sm2);
    int tid = threadIdx.x;
    int wid = tid >> 5, lid = tid & 31;
    int wm = wid & 3, wn = wid >> 2;            // warp tile 32m x 64n
    int nt0 = blockIdx.x, mt0 = blockIdx.y;
    int mbase = mt0*128;
    int b = mbase / NT;
    int d0 = nt0*128;

    const __nv_bfloat16* ah = g_chi + (size_t)mbase*NH;
    const __nv_bfloat16* al = g_clo + (size_t)mbase*NH;
    const __nv_bfloat16* bh = g_wothi + (size_t)b*HC + (size_t)d0*NH;
    const __nv_bfloat16* bl = g_wotlo + (size_t)b*HC + (size_t)d0*NH;

    #pragma unroll
    for (int i=0;i<16;i++){
        int u = tid + i*256;
        int sel = u>>10, w = u & 1023;
        int row = w>>3, seg = w&7;
        uint32_t off = SWZ(row*128 + seg*16);
        const __nv_bfloat16* src = (sel==0?ah:(sel==1?al:(sel==2?bh:bl))) + (size_t)row*NH + seg*8;
        uint32_t base = (sel==0?G2_A_HI:(sel==1?G2_A_LO:(sel==2?G2_B_HI:G2_B_LO)));
        CPA16(sb + base + off, src);
    }
    CPC();
    CPW0();
    __syncthreads();

    float acc[2][8][4];
    #pragma unroll
    for (int mt=0;mt<2;mt++)
        #pragma unroll
        for (int nt=0;nt<8;nt++)
            #pragma unroll
            for (int q=0;q<4;q++) acc[mt][nt][q] = 0.f;

    #pragma unroll
    for (int kk=0;kk<4;kk++){
        uint32_t ahf[2][4], alf[2][4], bhf[8][2], blf[8][2];
        #pragma unroll
        for (int mt=0;mt<2;mt++){
            int row = wm*32 + mt*16 + (lid&15);
            uint32_t off = SWZ(row*128 + kk*32 + (lid>>4)*16);
            ldsm_x4(sb + G2_A_HI + off, ahf[mt][0],ahf[mt][1],ahf[mt][2],ahf[mt][3]);
            ldsm_x4(sb + G2_A_LO + off, alf[mt][0],alf[mt][1],alf[mt][2],alf[mt][3]);
        }
        #pragma unroll
        for (int ng=0;ng<4;ng++){
            int row = wn*64 + ng*16 + (lid&7) + ((lid>>4)<<3);
            uint32_t off = SWZ(row*128 + kk*32 + ((lid>>3)&1)*16);
            ldsm_x4(sb + G2_B_HI + off, bhf[2*ng][0], bhf[2*ng][1], bhf[2*ng+1][0], bhf[2*ng+1][1]);
            ldsm_x4(sb + G2_B_LO + off, blf[2*ng][0], blf[2*ng][1], blf[2*ng+1][0], blf[2*ng+1][1]);
        }
        #pragma unroll
        for (int mt=0;mt<2;mt++){
            #pragma unroll
            for (int nt=0;nt<8;nt++){
                mma_bf16(acc[mt][nt], ahf[mt][0],ahf[mt][1],ahf[mt][2],ahf[mt][3], bhf[nt][0],bhf[nt][1]);
                mma_bf16(acc[mt][nt], ahf[mt][0],ahf[mt][1],ahf[mt][2],ahf[mt][3], blf[nt][0],blf[nt][1]);
                mma_bf16(acc[mt][nt], alf[mt][0],alf[mt][1],alf[mt][2],alf[mt][3], bhf[nt][0],bhf[nt][1]);
            }
        }
    }

    #pragma unroll
    for (int mt=0;mt<2;mt++){
        #pragma unroll
        for (int nt=0;nt<8;nt++){
            float* c = acc[mt][nt];
            int row = mbase + wm*32 + mt*16 + (lid>>2);
            int col = d0 + wn*64 + nt*8 + (lid&3)*2;
            *(float2*)(out + (size_t)row*NC + col)       = make_float2(c[0], c[1]);
            *(float2*)(out + (size_t)(row+8)*NC + col)   = make_float2(c[2], c[3]);
        }
    }
}

// ---------------- launch ----------------
extern "C" void kernel_launch(void* const* d_in, const int* in_sizes, int n_in,
                              void* d_out, int out_size){
    const float* X     = (const float*)d_in[0];
    const float* sim   = (const float*)d_in[1];
    const float* gates = (const float*)d_in[2];
    const float* w_v   = (const float*)d_in[5];
    const float* o_w   = (const float*)d_in[6];
    float* out = (float*)d_out;

    static int attr_done = 0;
    if (!attr_done){
        cudaFuncSetAttribute(k_gemm1_tc, cudaFuncAttributeMaxDynamicSharedMemorySize, G1_SMEM);
        cudaFuncSetAttribute(k_gemm2_tc, cudaFuncAttributeMaxDynamicSharedMemorySize, G2_SMEM);
        attr_done = 1;
    }

    k_mean     <<<dim3(NC/256, 16, NB), 256>>>(X);
    k_dots     <<<NE + NB + NB*NE, 128>>>(sim);
    k_weff     <<<HC/256, 256>>>(gates, w_v, o_w);
    k_trans2   <<<dim3(NC/64, NB), 256>>>();
    k_gemm1_tc <<<dim3(NT/64, NB), 256, G1_SMEM>>>(X);
    k_gemm2_tc <<<dim3(NC/128, NROWS/128), 256, G2_SMEM>>>(out);
    (void)in_sizes; (void)n_in; (void)out_size;
}

// round 13
// speedup vs baseline: 2.1052x; 1.2278x over previous
#include <cuda_runtime.h>
#include <cuda_fp16.h>
#include <math.h>
#include <float.h>
#include <stdint.h>

#define NB 8
#define NT 2048
#define NC 2048
#define NE 32
#define NH 64
#define HC (NH*NC)
#define NROWS (NB*NT)

// ---------------- scratch (device globals; no allocation allowed) ----------------
__device__ __align__(16) float g_part[NB*16*NC];
__device__ float g_dots[NE + NB + NB*NE];
__device__ __align__(16) __half g_wvhi[NB*HC];             // Wv_eff fp16 (b,h,c)
__device__ __align__(16) float  g_wo[NB*HC];               // Wo_eff fp32 (b,h,c)
__device__ __align__(16) __half g_wothi[NB*HC];            // Wo_eff^T fp16 (b,d,h)
__device__ __align__(16) __half g_chi[(size_t)NROWS*NH];   // comb hi (row,h)
__device__ __align__(16) __half g_clo[(size_t)NROWS*NH];   // comb lo (row,h)

// ---------------- helpers ----------------
__device__ __forceinline__ uint32_t smem_u32(const void* p){
    uint32_t a;
    asm("{ .reg .u64 t; cvta.to.shared.u64 t, %1; cvt.u32.u64 %0, t; }" : "=r"(a) : "l"(p));
    return a;
}
#define SWZ(x) ((x) ^ (((x)>>3)&0x70))
#define CPA16(dst,src) asm volatile("cp.async.cg.shared.global [%0], [%1], 16;" :: "r"(dst), "l"(src))
#define CPC() asm volatile("cp.async.commit_group;")
#define CPW1() asm volatile("cp.async.wait_group 1;")
#define CPW0() asm volatile("cp.async.wait_group 0;")

__device__ __forceinline__ void ldsm_x4(uint32_t a, uint32_t& r0, uint32_t& r1, uint32_t& r2, uint32_t& r3){
    asm volatile("ldmatrix.sync.aligned.m8n8.x4.shared.b16 {%0,%1,%2,%3}, [%4];"
        : "=r"(r0),"=r"(r1),"=r"(r2),"=r"(r3) : "r"(a));
}
__device__ __forceinline__ float2 lds64(uint32_t a){
    float2 f;
    asm volatile("ld.shared.v2.f32 {%0,%1}, [%2];" : "=f"(f.x), "=f"(f.y) : "r"(a));
    return f;
}
__device__ __forceinline__ void mma_f16(float* c, uint32_t a0,uint32_t a1,uint32_t a2,uint32_t a3,
                                        uint32_t b0,uint32_t b1){
    asm volatile("mma.sync.aligned.m16n8k16.row.col.f32.f16.f16.f32 "
        "{%0,%1,%2,%3}, {%4,%5,%6,%7}, {%8,%9}, {%0,%1,%2,%3};"
        : "+f"(c[0]),"+f"(c[1]),"+f"(c[2]),"+f"(c[3])
        : "r"(a0),"r"(a1),"r"(a2),"r"(a3),"r"(b0),"r"(b1));
}
__device__ __forceinline__ float wredsum(float v){
    #pragma unroll
    for (int o=16;o>0;o>>=1) v += __shfl_xor_sync(0xffffffffu, v, o);
    return v;
}
__device__ __forceinline__ float wredmax(float v){
    #pragma unroll
    for (int o=16;o>0;o>>=1) v = fmaxf(v, __shfl_xor_sync(0xffffffffu, v, o));
    return v;
}
// split fp32 pair into packed fp16x2 hi and lo
__device__ __forceinline__ void splitpack2h(float2 f, uint32_t& hi, uint32_t& lo){
    __half2 h2 = __floats2half2_rn(f.x, f.y);
    float2 hf = __half22float2(h2);
    __half2 l2 = __floats2half2_rn(f.x - hf.x, f.y - hf.y);
    hi = *reinterpret_cast<uint32_t*>(&h2);
    lo = *reinterpret_cast<uint32_t*>(&l2);
}

// ---------------- 1) mean pass: column sums only ----------------
__global__ void k_mean(const float* __restrict__ X){
    int c = blockIdx.x*256 + threadIdx.x;
    int s = blockIdx.y, b = blockIdx.z;
    const float* p = X + ((size_t)b*NT + (size_t)s*128)*NC + c;
    float a0=0.f,a1=0.f,a2=0.f,a3=0.f;
    for (int t=0;t<128;t+=4){
        a0 += p[0]; a1 += p[NC]; a2 += p[2*NC]; a3 += p[3*NC];
        p += (size_t)4*NC;
    }
    g_part[(b*16+s)*NC + c] = (a0+a1)+(a2+a3);
}

// ---------------- 2) norms + affinity dots ----------------
__global__ void k_dots(const float* __restrict__ sim){
    __shared__ float sred[4];
    int task = blockIdx.x;
    int tid = threadIdx.x;
    float acc = 0.f;
    if (task < NE){
        int e = task;
        for (int c = tid; c < NC; c += 128){ float v = sim[c*NE + e]; acc += v*v; }
    } else if (task < NE+NB){
        int b = task - NE;
        for (int c = tid; c < NC; c += 128){
            float v = 0.f;
            #pragma unroll
            for (int s=0;s<16;s++) v += g_part[(b*16+s)*NC + c];
            acc += v*v;
        }
    } else {
        int p = task - NE - NB;
        int b = p >> 5, e = p & 31;
        for (int c = tid; c < NC; c += 128){
            float v = 0.f;
            #pragma unroll
            for (int s=0;s<16;s++) v += g_part[(b*16+s)*NC + c];
            acc += v * sim[c*NE + e];
        }
    }
    acc = wredsum(acc);
    if ((tid & 31) == 0) sred[tid>>5] = acc;
    __syncthreads();
    if (tid == 0) g_dots[task] = (sred[0]+sred[1])+(sred[2]+sred[3]);
}

// ---------------- 3) gating + fold; Wv to fp16, Wo kept fp32 ----------------
__global__ void k_weff(const float* __restrict__ gates,
                       const float* __restrict__ w_v, const float* __restrict__ o_w){
    __shared__ float r[NB*NE];
    int tid = threadIdx.x;
    {
        int lane = tid & 31, b = tid >> 5;
        float nsim2 = g_dots[lane];
        float nseq2 = g_dots[NE + b];
        float dot   = g_dots[NE + NB + b*NE + lane];
        float aff = dot / sqrtf(nsim2 * nseq2);
        float sig = 1.f / (1.f + expf(-gates[lane]));
        float logit = aff - sig;
        float gated = fmaxf(logit, 0.f);
        bool  act = gated > 0.f;
        unsigned actm = __ballot_sync(0xffffffffu, act);
        bool use = act;
        if (actm == 0u){
            int rank = 0;
            #pragma unroll
            for (int e=0;e<NE;e++){
                float le = __shfl_sync(0xffffffffu, logit, e);
                rank += (le > logit) || (le == logit && e < lane);
            }
            use = rank < 16;
        }
        float v = use ? gated : -FLT_MAX;
        float mx = wredmax(v);
        float ex = use ? expf(gated - mx) : 0.f;
        float sm = wredsum(ex);
        r[tid] = ex / sm;
    }
    __syncthreads();
    int j = blockIdx.x*256 + tid;
    float accv[NB], acco[NB];
    #pragma unroll
    for (int b=0;b<NB;b++){ accv[b]=0.f; acco[b]=0.f; }
    for (int e=0;e<NE;e++){
        float wv = w_v[(size_t)e*HC + j];
        float wo = o_w[(size_t)e*HC + j];
        #pragma unroll
        for (int b=0;b<NB;b++){
            float rr = r[b*NE+e];
            accv[b] = fmaf(rr, wv, accv[b]);
            acco[b] = fmaf(rr, wo, acco[b]);
        }
    }
    #pragma unroll
    for (int b=0;b<NB;b++){
        g_wvhi[(size_t)b*HC + j] = __float2half_rn(accv[b]);
        g_wo[(size_t)b*HC + j] = acco[b];
    }
}

// ---------------- 3b) transpose Wo_eff (b,h,d) -> (b,d,h) fp16 ----------------
__global__ void k_trans2(){
    __shared__ float ts[64][65];
    int b = blockIdx.y, d0 = blockIdx.x*64;
    int tid = threadIdx.x;
    int cc = tid & 63, q = tid >> 6;
    #pragma unroll
    for (int i=0;i<16;i++){
        int h = i*4 + q;
        ts[h][cc] = g_wo[(size_t)b*HC + (size_t)h*NC + d0 + cc];
    }
    __syncthreads();
    #pragma unroll
    for (int i=0;i<16;i++){
        int d = i*4 + q;
        g_wothi[(size_t)b*HC + (size_t)(d0+d)*NH + cc] = __float2half_rn(ts[cc][d]);
    }
}

// ---------------- GEMM1 smem: 3 stages x 24KB (A fp32 16KB + B hi 8KB) ----------------
#define G1_A     0
#define G1_B_HI  16384
#define G1_STG   24576
#define G1_SMEM  (3*G1_STG)

// A tile stored as 128 half-rows (srow = row*2 + k/32) of 32 fp32 (128B), SW128 swizzled
__device__ __forceinline__ uint32_t a_addr(uint32_t base, int row, int k){
    int srow = row*2 + (k>>5);
    int kin = k & 31;
    return base + srow*128 + (((kin>>2) ^ (srow&7))*16) + (kin&3)*4;
}

__device__ __forceinline__ void g1_load(uint32_t stg, const float* X4,
        const __half* bh, int ck, int tid){
    int c0 = ck*64;
    // A: 64 rows x 64 fp32 = 1024 x 16B granules
    #pragma unroll
    for (int i=0;i<4;i++){
        int u = tid + i*256;
        int row = u>>4, g = u&15;
        int srow = row*2 + (g>>3);
        uint32_t dst = stg + G1_A + srow*128 + (((g&7) ^ (srow&7))*16);
        CPA16(dst, X4 + (size_t)row*NC + c0 + g*4);
    }
    // B hi: 64n x 64k fp16 = 512 granules
    #pragma unroll
    for (int i=0;i<2;i++){
        int u = tid + i*256;
        int n = u>>3, seg = u&7;
        uint32_t dst = stg + G1_B_HI + SWZ(n*128 + seg*16);
        CPA16(dst, bh + (size_t)n*NC + c0 + seg*8);
    }
    CPC();
}

// ---------------- 4) GEMM1: comb = X @ Wv_hi^T (in-register fp16 split A, HMMA) ----------------
// block tile 64m x 64n, 256 threads, warp grid 4m x 2n, warp tile 16m x 32n
__global__ void __launch_bounds__(256, 2) k_gemm1_tc(const float* __restrict__ X){
    extern __shared__ __align__(1024) char sm1[];
    uint32_t sb = smem_u32(sm1);
    int tid = threadIdx.x;
    int wid = tid >> 5, lid = tid & 31;
    int wm = wid & 3, wn = wid >> 2;
    int mt0 = blockIdx.x, b = blockIdx.y;
    int t0 = mt0*64;

    const float* Xg = X + ((size_t)(b*NT + t0))*NC;
    const __half* bh = g_wvhi + (size_t)b*HC;

    float acc[4][4];
    #pragma unroll
    for (int nt=0;nt<4;nt++)
        #pragma unroll
        for (int q=0;q<4;q++) acc[nt][q] = 0.f;

    g1_load(sb + 0*G1_STG, Xg, bh, 0, tid);
    g1_load(sb + 1*G1_STG, Xg, bh, 1, tid);

    int ar = wm*16 + (lid>>2);     // A row within tile
    int akc = (lid&3)*2;           // A col base within k16

    for (int t=0;t<32;t++){
        if (t < 31) { CPW1(); } else { CPW0(); }
        __syncthreads();
        if (t+2 < 32) g1_load(sb + ((t+2)%3)*G1_STG, Xg, bh, t+2, tid);
        uint32_t stg = sb + (t%3)*G1_STG;
        #pragma unroll
        for (int kk=0;kk<4;kk++){
            int kb = kk*16 + akc;
            uint32_t ah[4], al[4];
            {
                float2 p0 = lds64(a_addr(stg + G1_A, ar,   kb));
                float2 p1 = lds64(a_addr(stg + G1_A, ar+8, kb));
                float2 p2 = lds64(a_addr(stg + G1_A, ar,   kb+8));
                float2 p3 = lds64(a_addr(stg + G1_A, ar+8, kb+8));
                splitpack2h(p0, ah[0], al[0]);
                splitpack2h(p1, ah[1], al[1]);
                splitpack2h(p2, ah[2], al[2]);
                splitpack2h(p3, ah[3], al[3]);
            }
            uint32_t bhf[4][2];
            #pragma unroll
            for (int ng=0;ng<2;ng++){
                int row = wn*32 + ng*16 + (lid&7) + ((lid>>4)<<3);
                uint32_t off = SWZ(row*128 + kk*32 + ((lid>>3)&1)*16);
                ldsm_x4(stg + G1_B_HI + off, bhf[2*ng][0], bhf[2*ng][1], bhf[2*ng+1][0], bhf[2*ng+1][1]);
            }
            #pragma unroll
            for (int nt=0;nt<4;nt++){
                mma_f16(acc[nt], ah[0],ah[1],ah[2],ah[3], bhf[nt][0],bhf[nt][1]);
                mma_f16(acc[nt], al[0],al[1],al[2],al[3], bhf[nt][0],bhf[nt][1]);
            }
        }
    }

    // epilogue: split acc -> g_chi/g_clo (fp16 hi/lo)
    #pragma unroll
    for (int nt=0;nt<4;nt++){
        float* c = acc[nt];
        int row = b*NT + t0 + wm*16 + (lid>>2);
        int col = wn*32 + nt*8 + (lid&3)*2;
        #pragma unroll
        for (int h2=0;h2<2;h2++){
            int rr = row + h2*8;
            uint32_t uh, ul;
            splitpack2h(make_float2(c[2*h2], c[2*h2+1]), uh, ul);
            *(uint32_t*)(g_chi + (size_t)rr*NH + col) = uh;
            *(uint32_t*)(g_clo + (size_t)rr*NH + col) = ul;
        }
    }
}

// ---------------- GEMM2 smem layout: 48KB single shot ----------------
#define G2_A_HI  0
#define G2_A_LO  16384
#define G2_B_HI  32768
#define G2_SMEM  49152

// ---------------- 5) GEMM2: out = comb @ Wo_hi (fp16 split A, HMMA) ----------------
__global__ void __launch_bounds__(256, 2) k_gemm2_tc(float* __restrict__ out){
    extern __shared__ __align__(1024) char sm2[];
    uint32_t sb = smem_u32(sm2);
    int tid = threadIdx.x;
    int wid = tid >> 5, lid = tid & 31;
    int wm = wid & 3, wn = wid >> 2;            // warp tile 32m x 64n
    int nt0 = blockIdx.x, mt0 = blockIdx.y;
    int mbase = mt0*128;
    int b = mbase / NT;
    int d0 = nt0*128;

    const __half* ah = g_chi + (size_t)mbase*NH;
    const __half* al = g_clo + (size_t)mbase*NH;
    const __half* bh = g_wothi + (size_t)b*HC + (size_t)d0*NH;

    #pragma unroll
    for (int i=0;i<12;i++){
        int u = tid + i*256;
        int sel = u>>10, w = u & 1023;
        int row = w>>3, seg = w&7;
        uint32_t off = SWZ(row*128 + seg*16);
        const __half* src = (sel==0?ah:(sel==1?al:bh)) + (size_t)row*NH + seg*8;
        uint32_t base = (sel==0?G2_A_HI:(sel==1?G2_A_LO:G2_B_HI));
        CPA16(sb + base + off, src);
    }
    CPC();
    CPW0();
    __syncthreads();

    float acc[2][8][4];
    #pragma unroll
    for (int mt=0;mt<2;mt++)
        #pragma unroll
        for (int nt=0;nt<8;nt++)
            #pragma unroll
            for (int q=0;q<4;q++) acc[mt][nt][q] = 0.f;

    #pragma unroll
    for (int kk=0;kk<4;kk++){
        uint32_t ahf[2][4], alf[2][4], bhf[8][2];
        #pragma unroll
        for (int mt=0;mt<2;mt++){
            int row = wm*32 + mt*16 + (lid&15);
            uint32_t off = SWZ(row*128 + kk*32 + (lid>>4)*16);
            ldsm_x4(sb + G2_A_HI + off, ahf[mt][0],ahf[mt][1],ahf[mt][2],ahf[mt][3]);
            ldsm_x4(sb + G2_A_LO + off, alf[mt][0],alf[mt][1],alf[mt][2],alf[mt][3]);
        }
        #pragma unroll
        for (int ng=0;ng<4;ng++){
            int row = wn*64 + ng*16 + (lid&7) + ((lid>>4)<<3);
            uint32_t off = SWZ(row*128 + kk*32 + ((lid>>3)&1)*16);
            ldsm_x4(sb + G2_B_HI + off, bhf[2*ng][0], bhf[2*ng][1], bhf[2*ng+1][0], bhf[2*ng+1][1]);
        }
        #pragma unroll
        for (int mt=0;mt<2;mt++){
            #pragma unroll
            for (int nt=0;nt<8;nt++){
                mma_f16(acc[mt][nt], ahf[mt][0],ahf[mt][1],ahf[mt][2],ahf[mt][3], bhf[nt][0],bhf[nt][1]);
                mma_f16(acc[mt][nt], alf[mt][0],alf[mt][1],alf[mt][2],alf[mt][3], bhf[nt][0],bhf[nt][1]);
            }
        }
    }

    #pragma unroll
    for (int mt=0;mt<2;mt++){
        #pragma unroll
        for (int nt=0;nt<8;nt++){
            float* c = acc[mt][nt];
            int row = mbase + wm*32 + mt*16 + (lid>>2);
            int col = d0 + wn*64 + nt*8 + (lid&3)*2;
            *(float2*)(out + (size_t)row*NC + col)       = make_float2(c[0], c[1]);
            *(float2*)(out + (size_t)(row+8)*NC + col)   = make_float2(c[2], c[3]);
        }
    }
}

// ---------------- launch ----------------
extern "C" void kernel_launch(void* const* d_in, const int* in_sizes, int n_in,
                              void* d_out, int out_size){
    const float* X     = (const float*)d_in[0];
    const float* sim   = (const float*)d_in[1];
    const float* gates = (const float*)d_in[2];
    const float* w_v   = (const float*)d_in[5];
    const float* o_w   = (const float*)d_in[6];
    float* out = (float*)d_out;

    static int attr_done = 0;
    if (!attr_done){
        cudaFuncSetAttribute(k_gemm1_tc, cudaFuncAttributeMaxDynamicSharedMemorySize, G1_SMEM);
        cudaFuncSetAttribute(k_gemm2_tc, cudaFuncAttributeMaxDynamicSharedMemorySize, G2_SMEM);
        attr_done = 1;
    }

    k_mean     <<<dim3(NC/256, 16, NB), 256>>>(X);
    k_dots     <<<NE + NB + NB*NE, 128>>>(sim);
    k_weff     <<<HC/256, 256>>>(gates, w_v, o_w);
    k_trans2   <<<dim3(NC/64, NB), 256>>>();
    k_gemm1_tc <<<dim3(NT/64, NB), 256, G1_SMEM>>>(X);
    k_gemm2_tc <<<dim3(NC/128, NROWS/128), 256, G2_SMEM>>>(out);
    (void)in_sizes; (void)n_in; (void)out_size;
}

// round 14
// speedup vs baseline: 2.2338x; 1.0611x over previous
#include <cuda_runtime.h>
#include <cuda_fp16.h>
#include <math.h>
#include <float.h>
#include <stdint.h>

#define NB 8
#define NT 2048
#define NC 2048
#define NE 32
#define NH 64
#define HC (NH*NC)
#define NROWS (NB*NT)

// ---------------- scratch (device globals; no allocation allowed) ----------------
__device__ __align__(16) float g_part[NB*16*NC];
__device__ float g_dots[NE + NB + NB*NE];
__device__ __align__(16) __half g_wvhi[NB*HC];             // Wv_eff fp16 (b,h,c)
__device__ __align__(16) float  g_wo[NB*HC];               // Wo_eff fp32 (b,h,c)
__device__ __align__(16) __half g_wothi[NB*HC];            // Wo_eff^T fp16 (b,d,h)
__device__ __align__(16) __half g_chi[(size_t)NROWS*NH];   // comb fp16 (row,h)

// ---------------- helpers ----------------
__device__ __forceinline__ uint32_t smem_u32(const void* p){
    uint32_t a;
    asm("{ .reg .u64 t; cvta.to.shared.u64 t, %1; cvt.u32.u64 %0, t; }" : "=r"(a) : "l"(p));
    return a;
}
#define SWZ(x) ((x) ^ (((x)>>3)&0x70))
#define CPA16(dst,src) asm volatile("cp.async.cg.shared.global [%0], [%1], 16;" :: "r"(dst), "l"(src))
#define CPC() asm volatile("cp.async.commit_group;")
#define CPW1() asm volatile("cp.async.wait_group 1;")
#define CPW0() asm volatile("cp.async.wait_group 0;")

__device__ __forceinline__ void ldsm_x4(uint32_t a, uint32_t& r0, uint32_t& r1, uint32_t& r2, uint32_t& r3){
    asm volatile("ldmatrix.sync.aligned.m8n8.x4.shared.b16 {%0,%1,%2,%3}, [%4];"
        : "=r"(r0),"=r"(r1),"=r"(r2),"=r"(r3) : "r"(a));
}
__device__ __forceinline__ float2 lds64(uint32_t a){
    float2 f;
    asm volatile("ld.shared.v2.f32 {%0,%1}, [%2];" : "=f"(f.x), "=f"(f.y) : "r"(a));
    return f;
}
__device__ __forceinline__ void mma_f16(float* c, uint32_t a0,uint32_t a1,uint32_t a2,uint32_t a3,
                                        uint32_t b0,uint32_t b1){
    asm volatile("mma.sync.aligned.m16n8k16.row.col.f32.f16.f16.f32 "
        "{%0,%1,%2,%3}, {%4,%5,%6,%7}, {%8,%9}, {%0,%1,%2,%3};"
        : "+f"(c[0]),"+f"(c[1]),"+f"(c[2]),"+f"(c[3])
        : "r"(a0),"r"(a1),"r"(a2),"r"(a3),"r"(b0),"r"(b1));
}
__device__ __forceinline__ float wredsum(float v){
    #pragma unroll
    for (int o=16;o>0;o>>=1) v += __shfl_xor_sync(0xffffffffu, v, o);
    return v;
}
__device__ __forceinline__ float wredmax(float v){
    #pragma unroll
    for (int o=16;o>0;o>>=1) v = fmaxf(v, __shfl_xor_sync(0xffffffffu, v, o));
    return v;
}
// pack fp32 pair into fp16x2
__device__ __forceinline__ uint32_t pack2h(float2 f){
    __half2 h2 = __floats2half2_rn(f.x, f.y);
    return *reinterpret_cast<uint32_t*>(&h2);
}

// ---------------- 1) mean pass: column sums only ----------------
__global__ void k_mean(const float* __restrict__ X){
    int c = blockIdx.x*256 + threadIdx.x;
    int s = blockIdx.y, b = blockIdx.z;
    const float* p = X + ((size_t)b*NT + (size_t)s*128)*NC + c;
    float a0=0.f,a1=0.f,a2=0.f,a3=0.f;
    for (int t=0;t<128;t+=4){
        a0 += p[0]; a1 += p[NC]; a2 += p[2*NC]; a3 += p[3*NC];
        p += (size_t)4*NC;
    }
    g_part[(b*16+s)*NC + c] = (a0+a1)+(a2+a3);
}

// ---------------- 2) norms + affinity dots ----------------
__global__ void k_dots(const float* __restrict__ sim){
    __shared__ float sred[4];
    int task = blockIdx.x;
    int tid = threadIdx.x;
    float acc = 0.f;
    if (task < NE){
        int e = task;
        for (int c = tid; c < NC; c += 128){ float v = sim[c*NE + e]; acc += v*v; }
    } else if (task < NE+NB){
        int b = task - NE;
        for (int c = tid; c < NC; c += 128){
            float v = 0.f;
            #pragma unroll
            for (int s=0;s<16;s++) v += g_part[(b*16+s)*NC + c];
            acc += v*v;
        }
    } else {
        int p = task - NE - NB;
        int b = p >> 5, e = p & 31;
        for (int c = tid; c < NC; c += 128){
            float v = 0.f;
            #pragma unroll
            for (int s=0;s<16;s++) v += g_part[(b*16+s)*NC + c];
            acc += v * sim[c*NE + e];
        }
    }
    acc = wredsum(acc);
    if ((tid & 31) == 0) sred[tid>>5] = acc;
    __syncthreads();
    if (tid == 0) g_dots[task] = (sred[0]+sred[1])+(sred[2]+sred[3]);
}

// ---------------- 3) gating + fold; Wv to fp16, Wo kept fp32 ----------------
__global__ void k_weff(const float* __restrict__ gates,
                       const float* __restrict__ w_v, const float* __restrict__ o_w){
    __shared__ float r[NB*NE];
    int tid = threadIdx.x;
    {
        int lane = tid & 31, b = tid >> 5;
        float nsim2 = g_dots[lane];
        float nseq2 = g_dots[NE + b];
        float dot   = g_dots[NE + NB + b*NE + lane];
        float aff = dot / sqrtf(nsim2 * nseq2);
        float sig = 1.f / (1.f + expf(-gates[lane]));
        float logit = aff - sig;
        float gated = fmaxf(logit, 0.f);
        bool  act = gated > 0.f;
        unsigned actm = __ballot_sync(0xffffffffu, act);
        bool use = act;
        if (actm == 0u){
            int rank = 0;
            #pragma unroll
            for (int e=0;e<NE;e++){
                float le = __shfl_sync(0xffffffffu, logit, e);
                rank += (le > logit) || (le == logit && e < lane);
            }
            use = rank < 16;
        }
        float v = use ? gated : -FLT_MAX;
        float mx = wredmax(v);
        float ex = use ? expf(gated - mx) : 0.f;
        float sm = wredsum(ex);
        r[tid] = ex / sm;
    }
    __syncthreads();
    int j = blockIdx.x*256 + tid;
    float accv[NB], acco[NB];
    #pragma unroll
    for (int b=0;b<NB;b++){ accv[b]=0.f; acco[b]=0.f; }
    for (int e=0;e<NE;e++){
        float wv = w_v[(size_t)e*HC + j];
        float wo = o_w[(size_t)e*HC + j];
        #pragma unroll
        for (int b=0;b<NB;b++){
            float rr = r[b*NE+e];
            accv[b] = fmaf(rr, wv, accv[b]);
            acco[b] = fmaf(rr, wo, acco[b]);
        }
    }
    #pragma unroll
    for (int b=0;b<NB;b++){
        g_wvhi[(size_t)b*HC + j] = __float2half_rn(accv[b]);
        g_wo[(size_t)b*HC + j] = acco[b];
    }
}

// ---------------- 3b) transpose Wo_eff (b,h,d) -> (b,d,h) fp16 ----------------
__global__ void k_trans2(){
    __shared__ float ts[64][65];
    int b = blockIdx.y, d0 = blockIdx.x*64;
    int tid = threadIdx.x;
    int cc = tid & 63, q = tid >> 6;
    #pragma unroll
    for (int i=0;i<16;i++){
        int h = i*4 + q;
        ts[h][cc] = g_wo[(size_t)b*HC + (size_t)h*NC + d0 + cc];
    }
    __syncthreads();
    #pragma unroll
    for (int i=0;i<16;i++){
        int d = i*4 + q;
        g_wothi[(size_t)b*HC + (size_t)(d0+d)*NH + cc] = __float2half_rn(ts[cc][d]);
    }
}

// ---------------- GEMM1 smem: 3 stages x 24KB (A fp32 16KB + B hi 8KB) ----------------
#define G1_A     0
#define G1_B_HI  16384
#define G1_STG   24576
#define G1_SMEM  (3*G1_STG)

// A tile stored as 128 half-rows (srow = row*2 + k/32) of 32 fp32 (128B), SW128 swizzled
__device__ __forceinline__ uint32_t a_addr(uint32_t base, int row, int k){
    int srow = row*2 + (k>>5);
    int kin = k & 31;
    return base + srow*128 + (((kin>>2) ^ (srow&7))*16) + (kin&3)*4;
}

__device__ __forceinline__ void g1_load(uint32_t stg, const float* X4,
        const __half* bh, int ck, int tid){
    int c0 = ck*64;
    // A: 64 rows x 64 fp32 = 1024 x 16B granules
    #pragma unroll
    for (int i=0;i<4;i++){
        int u = tid + i*256;
        int row = u>>4, g = u&15;
        int srow = row*2 + (g>>3);
        uint32_t dst = stg + G1_A + srow*128 + (((g&7) ^ (srow&7))*16);
        CPA16(dst, X4 + (size_t)row*NC + c0 + g*4);
    }
    // B hi: 64n x 64k fp16 = 512 granules
    #pragma unroll
    for (int i=0;i<2;i++){
        int u = tid + i*256;
        int n = u>>3, seg = u&7;
        uint32_t dst = stg + G1_B_HI + SWZ(n*128 + seg*16);
        CPA16(dst, bh + (size_t)n*NC + c0 + seg*8);
    }
    CPC();
}

// ---------------- 4) GEMM1: comb = fp16(X) @ Wv_hi^T (HMMA) ----------------
// block tile 64m x 64n, 256 threads, warp grid 4m x 2n, warp tile 16m x 32n
__global__ void __launch_bounds__(256, 2) k_gemm1_tc(const float* __restrict__ X){
    extern __shared__ __align__(1024) char sm1[];
    uint32_t sb = smem_u32(sm1);
    int tid = threadIdx.x;
    int wid = tid >> 5, lid = tid & 31;
    int wm = wid & 3, wn = wid >> 2;
    int mt0 = blockIdx.x, b = blockIdx.y;
    int t0 = mt0*64;

    const float* Xg = X + ((size_t)(b*NT + t0))*NC;
    const __half* bh = g_wvhi + (size_t)b*HC;

    float acc[4][4];
    #pragma unroll
    for (int nt=0;nt<4;nt++)
        #pragma unroll
        for (int q=0;q<4;q++) acc[nt][q] = 0.f;

    g1_load(sb + 0*G1_STG, Xg, bh, 0, tid);
    g1_load(sb + 1*G1_STG, Xg, bh, 1, tid);

    int ar = wm*16 + (lid>>2);     // A row within tile
    int akc = (lid&3)*2;           // A col base within k16

    for (int t=0;t<32;t++){
        if (t < 31) { CPW1(); } else { CPW0(); }
        __syncthreads();
        if (t+2 < 32) g1_load(sb + ((t+2)%3)*G1_STG, Xg, bh, t+2, tid);
        uint32_t stg = sb + (t%3)*G1_STG;
        #pragma unroll
        for (int kk=0;kk<4;kk++){
            int kb = kk*16 + akc;
            uint32_t ah[4];
            {
                float2 p0 = lds64(a_addr(stg + G1_A, ar,   kb));
                float2 p1 = lds64(a_addr(stg + G1_A, ar+8, kb));
                float2 p2 = lds64(a_addr(stg + G1_A, ar,   kb+8));
                float2 p3 = lds64(a_addr(stg + G1_A, ar+8, kb+8));
                ah[0] = pack2h(p0);
                ah[1] = pack2h(p1);
                ah[2] = pack2h(p2);
                ah[3] = pack2h(p3);
            }
            uint32_t bhf[4][2];
            #pragma unroll
            for (int ng=0;ng<2;ng++){
                int row = wn*32 + ng*16 + (lid&7) + ((lid>>4)<<3);
                uint32_t off = SWZ(row*128 + kk*32 + ((lid>>3)&1)*16);
                ldsm_x4(stg + G1_B_HI + off, bhf[2*ng][0], bhf[2*ng][1], bhf[2*ng+1][0], bhf[2*ng+1][1]);
            }
            #pragma unroll
            for (int nt=0;nt<4;nt++){
                mma_f16(acc[nt], ah[0],ah[1],ah[2],ah[3], bhf[nt][0],bhf[nt][1]);
            }
        }
    }

    // epilogue: comb -> fp16
    #pragma unroll
    for (int nt=0;nt<4;nt++){
        float* c = acc[nt];
        int row = b*NT + t0 + wm*16 + (lid>>2);
        int col = wn*32 + nt*8 + (lid&3)*2;
        #pragma unroll
        for (int h2=0;h2<2;h2++){
            int rr = row + h2*8;
            *(uint32_t*)(g_chi + (size_t)rr*NH + col) = pack2h(make_float2(c[2*h2], c[2*h2+1]));
        }
    }
}

// ---------------- GEMM2 smem layout: 32KB single shot ----------------
#define G2_A_HI  0
#define G2_B_HI  16384
#define G2_SMEM  32768

// ---------------- 5) GEMM2: out = comb @ Wo_hi (HMMA) ----------------
__global__ void __launch_bounds__(256, 2) k_gemm2_tc(float* __restrict__ out){
    extern __shared__ __align__(1024) char sm2[];
    uint32_t sb = smem_u32(sm2);
    int tid = threadIdx.x;
    int wid = tid >> 5, lid = tid & 31;
    int wm = wid & 3, wn = wid >> 2;            // warp tile 32m x 64n
    int nt0 = blockIdx.x, mt0 = blockIdx.y;
    int mbase = mt0*128;
    int b = mbase / NT;
    int d0 = nt0*128;

    const __half* ah = g_chi + (size_t)mbase*NH;
    const __half* bh = g_wothi + (size_t)b*HC + (size_t)d0*NH;

    #pragma unroll
    for (int i=0;i<8;i++){
        int u = tid + i*256;
        int sel = u>>10, w = u & 1023;
        int row = w>>3, seg = w&7;
        uint32_t off = SWZ(row*128 + seg*16);
        const __half* src = (sel==0?ah:bh) + (size_t)row*NH + seg*8;
        uint32_t base = (sel==0?G2_A_HI:G2_B_HI);
        CPA16(sb + base + off, src);
    }
    CPC();
    CPW0();
    __syncthreads();

    float acc[2][8][4];
    #pragma unroll
    for (int mt=0;mt<2;mt++)
        #pragma unroll
        for (int nt=0;nt<8;nt++)
            #pragma unroll
            for (int q=0;q<4;q++) acc[mt][nt][q] = 0.f;

    #pragma unroll
    for (int kk=0;kk<4;kk++){
        uint32_t ahf[2][4], bhf[8][2];
        #pragma unroll
        for (int mt=0;mt<2;mt++){
            int row = wm*32 + mt*16 + (lid&15);
            uint32_t off = SWZ(row*128 + kk*32 + (lid>>4)*16);
            ldsm_x4(sb + G2_A_HI + off, ahf[mt][0],ahf[mt][1],ahf[mt][2],ahf[mt][3]);
        }
        #pragma unroll
        for (int ng=0;ng<4;ng++){
            int row = wn*64 + ng*16 + (lid&7) + ((lid>>4)<<3);
            uint32_t off = SWZ(row*128 + kk*32 + ((lid>>3)&1)*16);
            ldsm_x4(sb + G2_B_HI + off, bhf[2*ng][0], bhf[2*ng][1], bhf[2*ng+1][0], bhf[2*ng+1][1]);
        }
        #pragma unroll
        for (int mt=0;mt<2;mt++){
            #pragma unroll
            for (int nt=0;nt<8;nt++){
                mma_f16(acc[mt][nt], ahf[mt][0],ahf[mt][1],ahf[mt][2],ahf[mt][3], bhf[nt][0],bhf[nt][1]);
            }
        }
    }

    #pragma unroll
    for (int mt=0;mt<2;mt++){
        #pragma unroll
        for (int nt=0;nt<8;nt++){
            float* c = acc[mt][nt];
            int row = mbase + wm*32 + mt*16 + (lid>>2);
            int col = d0 + wn*64 + nt*8 + (lid&3)*2;
            *(float2*)(out + (size_t)row*NC + col)       = make_float2(c[0], c[1]);
            *(float2*)(out + (size_t)(row+8)*NC + col)   = make_float2(c[2], c[3]);
        }
    }
}

// ---------------- launch ----------------
extern "C" void kernel_launch(void* const* d_in, const int* in_sizes, int n_in,
                              void* d_out, int out_size){
    const float* X     = (const float*)d_in[0];
    const float* sim   = (const float*)d_in[1];
    const float* gates = (const float*)d_in[2];
    const float* w_v   = (const float*)d_in[5];
    const float* o_w   = (const float*)d_in[6];
    float* out = (float*)d_out;

    static int attr_done = 0;
    if (!attr_done){
        cudaFuncSetAttribute(k_gemm1_tc, cudaFuncAttributeMaxDynamicSharedMemorySize, G1_SMEM);
        cudaFuncSetAttribute(k_gemm2_tc, cudaFuncAttributeMaxDynamicSharedMemorySize, G2_SMEM);
        attr_done = 1;
    }

    k_mean     <<<dim3(NC/256, 16, NB), 256>>>(X);
    k_dots     <<<NE + NB + NB*NE, 128>>>(sim);
    k_weff     <<<HC/256, 256>>>(gates, w_v, o_w);
    k_trans2   <<<dim3(NC/64, NB), 256>>>();
    k_gemm1_tc <<<dim3(NT/64, NB), 256, G1_SMEM>>>(X);
    k_gemm2_tc <<<dim3(NC/128, NROWS/128), 256, G2_SMEM>>>(out);
    (void)in_sizes; (void)n_in; (void)out_size;
}